// round 4
// baseline (speedup 1.0000x reference)
#include <cuda_runtime.h>

#define DDEPTH 8
#define HDIM   4096
#define NT     512
#define NWARP  (NT / 32)      // 16
#define EPSV   1e-6f

// One CTA per (s,b) site. Each thread owns 8 contiguous hidden dims.
// ALL 8 depths loaded into registers up front (64 value regs/thread),
// single block reduction, softmax, register combine. No values smem.
__global__ __launch_bounds__(NT, 1)
void fullattnres_kernel(const float* __restrict__ values,
                        const float* __restrict__ query,
                        const float* __restrict__ weight,
                        float* __restrict__ out,
                        int SB)
{
    __shared__ float red[NWARP][17];   // [warp][scalar], padded stride 17
    __shared__ float fin[16];          // final: [0..7]=sumsq, [8..15]=dot

    const int tid  = threadIdx.x;
    const int lane = tid & 31;
    const int warp = tid >> 5;
    const int h    = tid * 8;

    const size_t base = (size_t)blockIdx.x * HDIM + h;
    const size_t dstr = (size_t)SB * HDIM;
    const float* p    = values + base;

    // fused q*w for this thread's 8 dims (L2-resident)
    const float4 q0 = *(const float4*)(query + h);
    const float4 q1 = *(const float4*)(query + h + 4);
    const float4 w0 = *(const float4*)(weight + h);
    const float4 w1 = *(const float4*)(weight + h + 4);
    const float4 qw0 = make_float4(q0.x*w0.x, q0.y*w0.y, q0.z*w0.z, q0.w*w0.w);
    const float4 qw1 = make_float4(q1.x*w1.x, q1.y*w1.y, q1.z*w1.z, q1.w*w1.w);

    // ── Load ALL depths up front: 16 independent LDG.128 per thread ──
    float4 va[DDEPTH], vb[DDEPTH];
    #pragma unroll
    for (int d = 0; d < DDEPTH; d++) {
        const float* pd = p + (size_t)d * dstr;
        va[d] = *(const float4*)(pd);
        vb[d] = *(const float4*)(pd + 4);
    }

    // per-thread partials for all depths
    float ss[DDEPTH], dp[DDEPTH];
    #pragma unroll
    for (int d = 0; d < DDEPTH; d++) {
        ss[d] = va[d].x*va[d].x + va[d].y*va[d].y + va[d].z*va[d].z + va[d].w*va[d].w
              + vb[d].x*vb[d].x + vb[d].y*vb[d].y + vb[d].z*vb[d].z + vb[d].w*vb[d].w;
        dp[d] = qw0.x*va[d].x + qw0.y*va[d].y + qw0.z*va[d].z + qw0.w*va[d].w
              + qw1.x*vb[d].x + qw1.y*vb[d].y + qw1.z*vb[d].z + qw1.w*vb[d].w;
    }

    // ── Stage 1: warp butterfly, 16 scalars ──
    #pragma unroll
    for (int off = 16; off > 0; off >>= 1) {
        #pragma unroll
        for (int d = 0; d < DDEPTH; d++) {
            ss[d] += __shfl_xor_sync(0xFFFFFFFFu, ss[d], off);
            dp[d] += __shfl_xor_sync(0xFFFFFFFFu, dp[d], off);
        }
    }
    if (lane == 0) {
        #pragma unroll
        for (int d = 0; d < DDEPTH; d++) {
            red[warp][d]     = ss[d];
            red[warp][8 + d] = dp[d];
        }
    }
    __syncthreads();

    // ── Stage 2: warp j reduces scalar j across the 16 warp partials ──
    // (16 warps, 16 scalars; lanes 16..31 mirror lanes 0..15, offsets <=8
    //  keep the butterfly inside each 16-group)
    {
        float x = red[lane & 15][warp];
        #pragma unroll
        for (int off = 8; off > 0; off >>= 1)
            x += __shfl_xor_sync(0xFFFFFFFFu, x, off);
        if (lane == 0) fin[warp] = x;
    }
    __syncthreads();

    // ── Softmax over depth (redundant per thread; broadcast LDS) ──
    float wt[DDEPTH];
    float mx = -3.402823466e38f;
    #pragma unroll
    for (int d = 0; d < DDEPTH; d++) {
        const float var   = fin[d] * (1.0f / HDIM);
        const float logit = fin[8 + d] * rsqrtf(var + EPSV);
        wt[d] = logit;
        mx = fmaxf(mx, logit);
    }
    float sum = 0.f;
    #pragma unroll
    for (int d = 0; d < DDEPTH; d++) {
        wt[d] = __expf(wt[d] - mx);
        sum += wt[d];
    }
    const float inv = 1.0f / sum;

    // ── Combine straight from registers ──
    float4 o0 = make_float4(0.f, 0.f, 0.f, 0.f);
    float4 o1 = make_float4(0.f, 0.f, 0.f, 0.f);
    #pragma unroll
    for (int d = 0; d < DDEPTH; d++) {
        const float wd = wt[d] * inv;
        o0.x += wd * va[d].x;  o0.y += wd * va[d].y;
        o0.z += wd * va[d].z;  o0.w += wd * va[d].w;
        o1.x += wd * vb[d].x;  o1.y += wd * vb[d].y;
        o1.z += wd * vb[d].z;  o1.w += wd * vb[d].w;
    }
    *(float4*)(out + base)     = o0;
    *(float4*)(out + base + 4) = o1;
}

extern "C" void kernel_launch(void* const* d_in, const int* in_sizes, int n_in,
                              void* d_out, int out_size)
{
    const float* values = (const float*)d_in[0];  // [D,S,B,H]
    const float* query  = (const float*)d_in[1];  // [H]
    const float* weight = (const float*)d_in[2];  // [H]
    float* out = (float*)d_out;                   // [S,B,H]

    const int H  = in_sizes[1];                   // 4096
    const int SB = out_size / H;                  // S*B = 4096

    fullattnres_kernel<<<SB, NT>>>(values, query, weight, out, SB);
}